// round 13
// baseline (speedup 1.0000x reference)
#include <cuda_runtime.h>
#include <cstdint>

#define B_  8
#define N_  512
#define F_  32
#define BN_ (B_ * N_)

#define STAGE_J     64                       // j's per pipeline stage
#define STAGE_BYTES (STAGE_J * F_ * 4)       // 8192 B
#define NBUF        4                        // SMEM ring buffers
#define NSTAGES     (N_ / STAGE_J)           // 8 stages per row
#define DEPTH       3                        // fills in flight (safe ordering)

#define PREPB       512                      // leading prep blocks (8 rows ea)
#define BLK_PER_BATCH 64                     // prep blocks per batch

// Scratch (allocation-free rule: __device__ globals)
__device__ float g_x1[BN_ * F_];
__device__ unsigned int g_cnt[B_];           // per-batch prep arrival counters

__device__ __forceinline__ uint32_t smem_u32(const void* p) {
    return (uint32_t)__cvta_generic_to_shared(p);
}

// ---------------------------------------------------------------------------
// Fused kernel.
//  blocks [0, PREPB):      prep — one warp per row (8 rows/block):
//        g_x1 = relu(relu(x@Wn1+bn1)@Wn2+bn2)
//        outX2 = relu(relu(x@Ws1+bs1)@Ws2+bs2)  (self path, RMW'd later)
//        fence -> per-batch counter arrive -> exit.
//  blocks [PREPB, PREPB+BN_): agg for row bi = blockIdx.x - PREPB:
//        x1-independent prologue (mbar init, DEPTH TMA fills of W, A row-sum)
//        -> spin on batch counter -> FROZEN 78us stream loop -> epilogue RMW.
//  Deadlock-safe: occupancy floor (regs<=64) gives wave-1 >= 592 blocks, and
//  prep bids are first in wave-1 placement, so all producers run at t=0.
// ---------------------------------------------------------------------------
__global__ __launch_bounds__(256)
void fused_kernel(const float* __restrict__ A, const float* __restrict__ W,
                  const float* __restrict__ x,
                  const float* __restrict__ Wn1, const float* __restrict__ bn1,
                  const float* __restrict__ Wn2, const float* __restrict__ bn2,
                  const float* __restrict__ Ws1, const float* __restrict__ bs1,
                  const float* __restrict__ Ws2, const float* __restrict__ bs2,
                  float* __restrict__ outW, float* __restrict__ outX2) {
    __shared__ __align__(128) float sbuf[NBUF][STAGE_J * F_];   // 32 KB
    __shared__ __align__(8) unsigned long long mbar[NBUF];
    __shared__ float sacc[8][F_];
    __shared__ float s_ws[8];
    __shared__ float s_inv;

    const unsigned FULL = 0xffffffffu;
    int tid  = threadIdx.x;
    int warp = tid >> 5;
    int lane = tid & 31;

    // ===================== PREP BLOCKS =====================
    if (blockIdx.x < PREPB) {
        int row = blockIdx.x * 8 + warp;      // 8 warps = 8 rows
        int f   = lane;

        float xv = x[row * F_ + f];

        float h  = bn1[f];
        float hs = bs1[f];
        #pragma unroll
        for (int k = 0; k < F_; k++) {
            float xk = __shfl_sync(FULL, xv, k);
            h  = fmaf(xk, Wn1[k * F_ + f], h);
            hs = fmaf(xk, Ws1[k * F_ + f], hs);
        }
        h  = fmaxf(h, 0.0f);
        hs = fmaxf(hs, 0.0f);

        float o1 = bn2[f];
        float o2 = bs2[f];
        #pragma unroll
        for (int k = 0; k < F_; k++) {
            o1 = fmaf(__shfl_sync(FULL, h,  k), Wn2[k * F_ + f], o1);
            o2 = fmaf(__shfl_sync(FULL, hs, k), Ws2[k * F_ + f], o2);
        }
        g_x1[row * F_ + f]  = fmaxf(o1, 0.0f);
        outX2[row * F_ + f] = fmaxf(o2, 0.0f);

        __threadfence();          // release: publish rows before arrive
        __syncthreads();
        if (tid == 0) {
            int batch = (int)(blockIdx.x >> 6);   // 64 blocks per batch
            atomicAdd(&g_cnt[batch], 1u);
        }
        return;
    }

    // ===================== AGG BLOCKS =====================
    int bi = (int)blockIdx.x - PREPB;  // row (b*N + i)
    int b  = bi >> 9;                  // N_ = 512
    int fq = lane & 7;
    int jo = lane >> 3;

    const char* Wrow = (const char*)(W    + (size_t)bi * N_ * F_);
    char*       Orow = (char*)      (outW + (size_t)bi * N_ * F_);
    const float4* x1p  = (const float4*)(g_x1 + (size_t)b * N_ * F_);
    const float*  Arow = A + (size_t)bi * N_;

    uint32_t sbuf_s = smem_u32(&sbuf[0][0]);
    uint32_t mbar_s = smem_u32(&mbar[0]);

    if (tid == 0) {
        #pragma unroll
        for (int i = 0; i < NBUF; i++)
            asm volatile("mbarrier.init.shared::cta.b64 [%0], 1;"
                         :: "r"(mbar_s + i * 8) : "memory");
    }
    __syncthreads();

    // prologue A: fill stages 0..DEPTH-1 (reads only W)
    if (tid == 0) {
        #pragma unroll
        for (int s = 0; s < DEPTH; s++) {
            uint32_t mb = mbar_s + s * 8;
            asm volatile("mbarrier.arrive.expect_tx.shared::cta.b64 _, [%0], %1;"
                         :: "r"(mb), "r"((uint32_t)STAGE_BYTES) : "memory");
            asm volatile(
                "cp.async.bulk.shared::cluster.global.mbarrier::complete_tx::bytes"
                " [%0], [%1], %2, [%3];"
                :: "r"(sbuf_s + s * STAGE_BYTES),
                   "l"(Wrow + (size_t)s * STAGE_BYTES),
                   "r"((uint32_t)STAGE_BYTES), "r"(mb) : "memory");
        }
    }

    // prologue B: A row-sum (reads only A; warms L1 for the loop's A loads)
    {
        float as = 0.0f;
        if (tid < 128) {                       // 128 float4 = 512 floats
            float4 av = ((const float4*)Arow)[tid];
            as = (av.x + av.y) + (av.z + av.w);
        }
        #pragma unroll
        for (int o = 16; o; o >>= 1) as += __shfl_xor_sync(FULL, as, o);
        if (lane == 0) s_ws[warp] = as;
        __syncthreads();
        if (tid == 0) {
            float rowsum = s_ws[0] + s_ws[1] + s_ws[2] + s_ws[3];
            s_inv = 1.0f / fmaxf(rowsum, 1e-12f);
        }
    }

    // wait for this batch's prep blocks (producers are wave-1-resident)
    if (tid == 0) {
        const unsigned int* cp = &g_cnt[b];
        unsigned int v;
        while (true) {
            asm volatile("ld.global.cg.u32 %0, [%1];" : "=r"(v) : "l"(cp));
            if (v >= BLK_PER_BATCH) break;
            __nanosleep(128);
        }
        __threadfence();          // acquire: order x1/outX2 reads after flag
    }
    __syncthreads();

    float4 acc = make_float4(0.0f, 0.0f, 0.0f, 0.0f);

    for (int s = 0; s < NSTAGES; s++) {
        int p = s & (NBUF - 1);
        uint32_t mb  = mbar_s + p * 8;
        uint32_t phs = (uint32_t)((s >> 2) & 1);

        // consumer wait (acquire) -- fill for stage s complete
        {
            uint32_t done;
            asm volatile(
                "{ .reg .pred q;\n\t"
                "mbarrier.try_wait.parity.acquire.cta.shared::cta.b64 q, [%1], %2;\n\t"
                "selp.b32 %0, 1, 0, q; }"
                : "=r"(done) : "r"(mb), "r"(phs) : "memory");
            if (!done) {
                asm volatile(
                    "{ .reg .pred q;\n\t"
                    "WL_%=:\n\t"
                    "mbarrier.try_wait.parity.acquire.cta.shared::cta.b64 q, [%0], %1, 0x989680;\n\t"
                    "@q bra.uni WD_%=;\n\t"
                    "bra.uni WL_%=;\n\t"
                    "WD_%=: }"
                    :: "r"(mb), "r"(phs) : "memory");
            }
        }

        uint32_t buf = sbuf_s + p * STAGE_BYTES;

        // compute: warp handles 8 j's of this 64-j stage (2 iters of 4 j)
        #pragma unroll
        for (int k = 0; k < 2; k++) {
            uint32_t a0_, a1_, a2_, a3_;
            asm volatile("ld.shared.v4.b32 {%0,%1,%2,%3}, [%4];"
                         : "=r"(a0_), "=r"(a1_), "=r"(a2_), "=r"(a3_)
                         : "r"(buf + warp * 1024 + k * 512 + lane * 16));
            float4 w4;
            w4.x = __uint_as_float(a0_); w4.y = __uint_as_float(a1_);
            w4.z = __uint_as_float(a2_); w4.w = __uint_as_float(a3_);
            int j = s * STAGE_J + warp * 8 + k * 4 + jo;
            float  a  = __ldg(Arow + j);          // L1-hot (prologue B)
            float4 xv = x1p[j * 8 + fq];          // fully coalesced 512B/warp
            acc.x = fmaf(a * w4.x, xv.x, acc.x);
            acc.y = fmaf(a * w4.y, xv.y, acc.y);
            acc.z = fmaf(a * w4.z, xv.z, acc.z);
            acc.w = fmaf(a * w4.w, xv.w, acc.w);
        }

        __syncthreads();   // all warps done reading buf p

        if (tid == 0) {
            // copy-out this stage (reads SMEM asynchronously)
            asm volatile("cp.async.bulk.global.shared::cta.bulk_group [%0], [%1], %2;"
                         :: "l"(Orow + (size_t)s * STAGE_BYTES),
                            "r"(buf), "r"((uint32_t)STAGE_BYTES) : "memory");
            asm volatile("cp.async.bulk.commit_group;" ::: "memory");

            int s2 = s + DEPTH;
            if (s2 < NSTAGES) {
                // refill target buf (s-1)&3: drain its copy-out group G_{s-1}
                asm volatile("cp.async.bulk.wait_group.read 1;" ::: "memory");
                int p2 = s2 & (NBUF - 1);
                uint32_t mb2 = mbar_s + p2 * 8;
                asm volatile("mbarrier.arrive.expect_tx.shared::cta.b64 _, [%0], %1;"
                             :: "r"(mb2), "r"((uint32_t)STAGE_BYTES) : "memory");
                asm volatile(
                    "cp.async.bulk.shared::cluster.global.mbarrier::complete_tx::bytes"
                    " [%0], [%1], %2, [%3];"
                    :: "r"(sbuf_s + p2 * STAGE_BYTES),
                       "l"(Wrow + (size_t)s2 * STAGE_BYTES),
                       "r"((uint32_t)STAGE_BYTES), "r"(mb2) : "memory");
            }
        }
    }

    // reduce across the 4 lanes sharing a feature-quad (xor 8, 16)
    #pragma unroll
    for (int o = 8; o <= 16; o <<= 1) {
        acc.x += __shfl_xor_sync(FULL, acc.x, o);
        acc.y += __shfl_xor_sync(FULL, acc.y, o);
        acc.z += __shfl_xor_sync(FULL, acc.z, o);
        acc.w += __shfl_xor_sync(FULL, acc.w, o);
    }
    if (lane < 8) {
        sacc[warp][lane * 4 + 0] = acc.x;
        sacc[warp][lane * 4 + 1] = acc.y;
        sacc[warp][lane * 4 + 2] = acc.z;
        sacc[warp][lane * 4 + 3] = acc.w;
    }
    __syncthreads();

    // block owns the full row: plain read-modify-write (prep stored xs here)
    if (tid < F_) {
        float ssum = 0.0f;
        #pragma unroll
        for (int w8 = 0; w8 < 8; w8++) ssum += sacc[w8][tid];
        float* dst = outX2 + (size_t)bi * F_ + tid;
        *dst = fmaf(ssum, s_inv, *dst);
    }
    // bulk stores drain at kernel completion
}

// ---------------------------------------------------------------------------
// Launch. Inputs (metadata order): A, W, x, Wn1, bn1, Wn2, bn2, Ws1, bs1,
// Ws2, bs2. Output: [W (B*N*N*F) | x2 (B*N*F)] as float32.
// Single fused kernel; per-batch counters reset via memset node each call.
// ---------------------------------------------------------------------------
extern "C" void kernel_launch(void* const* d_in, const int* in_sizes, int n_in,
                              void* d_out, int out_size) {
    const float* A   = (const float*)d_in[0];
    const float* W   = (const float*)d_in[1];
    const float* x   = (const float*)d_in[2];
    const float* Wn1 = (const float*)d_in[3];
    const float* bn1 = (const float*)d_in[4];
    const float* Wn2 = (const float*)d_in[5];
    const float* bn2 = (const float*)d_in[6];
    const float* Ws1 = (const float*)d_in[7];
    const float* bs1 = (const float*)d_in[8];
    const float* Ws2 = (const float*)d_in[9];
    const float* bs2 = (const float*)d_in[10];

    float* out   = (float*)d_out;
    float* outW  = out;
    float* outX2 = out + (size_t)B_ * N_ * N_ * F_;

    void* cnt_addr = nullptr;
    cudaGetSymbolAddress(&cnt_addr, g_cnt);
    cudaMemsetAsync(cnt_addr, 0, B_ * sizeof(unsigned int), 0);

    fused_kernel<<<PREPB + BN_, 256>>>(A, W, x, Wn1, bn1, Wn2, bn2,
                                       Ws1, bs1, Ws2, bs2, outW, outX2);
}